// round 7
// baseline (speedup 1.0000x reference)
#include <cuda_runtime.h>
#include <cuda_bf16.h>
#include <math.h>
#include <stdint.h>

// ---------------------------------------------------------------------------
// TransformerBlock: x[1,256,64,64]. N=4096 tokens, C=256, 8 heads, d=32.
// Attention + all GEMMs on mma.sync bf16 3-term (fp32-accurate).
// K/V are pre-split/pre-transposed in the QKV GEMM epilogue.
// ---------------------------------------------------------------------------

#define NTOK 4096
#define CDIM 256
#define HEADS 8
#define HDIM 32

__device__ float g_xl[NTOK * CDIM];
__device__ float g_qf[NTOK * CDIM];                      // Q fp32 [tok][c]
__device__ __nv_bfloat16 g_kh[HEADS * NTOK * HDIM];      // K hi [h][key][d]
__device__ __nv_bfloat16 g_kl[HEADS * NTOK * HDIM];
__device__ __nv_bfloat16 g_vh[HEADS * HDIM * NTOK];      // V hi [h][d][key]
__device__ __nv_bfloat16 g_vl[HEADS * HDIM * NTOK];
__device__ __nv_bfloat16 g_xn_hi[NTOK * CDIM],  g_xn_lo[NTOK * CDIM];
__device__ __nv_bfloat16 g_att_hi[NTOK * CDIM], g_att_lo[NTOK * CDIM];
__device__ __nv_bfloat16 g_h1_hi[NTOK * 4 * CDIM], g_h1_lo[NTOK * 4 * CDIM];
#define WOFF_QKV  0
#define WOFF_PROJ 196608
#define WOFF_MLP1 262144
#define WOFF_MLP2 524288
__device__ __nv_bfloat16 g_w_hi[786432], g_w_lo[786432];

// ============================ helpers ======================================
__device__ __forceinline__ uint16_t bf16_rn(float x) {
    __nv_bfloat16 h = __float2bfloat16(x);
    return *reinterpret_cast<uint16_t*>(&h);
}
__device__ __forceinline__ float bf16f(uint16_t u) {
    return __uint_as_float((uint32_t)u << 16);
}
__device__ __forceinline__ uint32_t pack2(uint16_t lo, uint16_t hi) {
    return (uint32_t)lo | ((uint32_t)hi << 16);
}
__device__ __forceinline__ void bfsplit2(float x, float y,
                                         uint32_t& hi, uint32_t& lo) {
    uint16_t hx = bf16_rn(x), hy = bf16_rn(y);
    hi = pack2(hx, hy);
    lo = pack2(bf16_rn(x - bf16f(hx)), bf16_rn(y - bf16f(hy)));
}

#define MMA(c, a, b0, b1)                                                      \
    asm volatile("mma.sync.aligned.m16n8k16.row.col.f32.bf16.bf16.f32 "        \
        "{%0,%1,%2,%3}, {%4,%5,%6,%7}, {%8,%9}, {%0,%1,%2,%3};"                \
        : "+f"((c)[0]), "+f"((c)[1]), "+f"((c)[2]), "+f"((c)[3])               \
        : "r"((a)[0]), "r"((a)[1]), "r"((a)[2]), "r"((a)[3]),                  \
          "r"(b0), "r"(b1))

__device__ __forceinline__ float exp2_fast(float y) {
    y = fmaxf(y, -126.0f);
    int ni = __float2int_rn(y);
    float f = y - (float)ni;
    float p = 1.5403530e-4f;
    p = fmaf(p, f, 1.33335581e-3f);
    p = fmaf(p, f, 9.61812911e-3f);
    p = fmaf(p, f, 5.55041087e-2f);
    p = fmaf(p, f, 2.40226507e-1f);
    p = fmaf(p, f, 6.93147181e-1f);
    p = fmaf(p, f, 1.0f);
    float sc = __int_as_float((ni + 127) << 23);
    return p * sc;
}

// ============================ small kernels ================================
__global__ void transpose_k(const float* __restrict__ src, float* __restrict__ dst,
                            int R, int C) {
    __shared__ float tile[32][33];
    int c0 = blockIdx.x * 32, r0 = blockIdx.y * 32;
    int x = threadIdx.x, y = threadIdx.y;
#pragma unroll
    for (int i = y; i < 32; i += 8)
        tile[i][x] = src[(size_t)(r0 + i) * C + c0 + x];
    __syncthreads();
#pragma unroll
    for (int i = y; i < 32; i += 8)
        dst[(size_t)(c0 + i) * R + r0 + x] = tile[x][i];
}

__global__ void wsplit_k(const float* __restrict__ src,
                         __nv_bfloat16* __restrict__ hi,
                         __nv_bfloat16* __restrict__ lo, int n) {
    int i = blockIdx.x * 256 + threadIdx.x;
    if (i < n) {
        float v = src[i];
        __nv_bfloat16 h = __float2bfloat16(v);
        hi[i] = h;
        lo[i] = __float2bfloat16(v - __bfloat162float(h));
    }
}

__global__ void ln_kernel(const float* __restrict__ in, const float* __restrict__ g,
                          const float* __restrict__ b,
                          __nv_bfloat16* __restrict__ ohi,
                          __nv_bfloat16* __restrict__ olo) {
    int n = blockIdx.x;
    int c = threadIdx.x;
    float v = in[n * CDIM + c];
    float s1 = v, s2 = v * v;
#pragma unroll
    for (int off = 16; off > 0; off >>= 1) {
        s1 += __shfl_xor_sync(0xFFFFFFFFu, s1, off);
        s2 += __shfl_xor_sync(0xFFFFFFFFu, s2, off);
    }
    __shared__ float sh1[8], sh2[8];
    int w = c >> 5, lane = c & 31;
    if (lane == 0) { sh1[w] = s1; sh2[w] = s2; }
    __syncthreads();
    float m1 = 0.f, m2 = 0.f;
#pragma unroll
    for (int i = 0; i < 8; i++) { m1 += sh1[i]; m2 += sh2[i]; }
    float mu = m1 * (1.f / CDIM);
    float var = m2 * (1.f / CDIM) - mu * mu;
    float rs = rsqrtf(var + 1e-5f);
    float y = (v - mu) * rs * g[c] + b[c];
    __nv_bfloat16 h = __float2bfloat16(y);
    ohi[n * CDIM + c] = h;
    olo[n * CDIM + c] = __float2bfloat16(y - __bfloat162float(h));
}

// ============================ bf16 3-term GEMM =============================
// EPI: 0 fp32 C; 1 GELU -> bf16 hi/lo; 2 +res fp32; 3 QKV scatter epilogue.
template <int EPI>
__global__ __launch_bounds__(128)
void hgemm_tn(const __nv_bfloat16* __restrict__ Ah, const __nv_bfloat16* __restrict__ Al,
              const __nv_bfloat16* __restrict__ Bh, const __nv_bfloat16* __restrict__ Bl,
              const float* __restrict__ bias, const float* __restrict__ res,
              float* __restrict__ Cf,
              __nv_bfloat16* __restrict__ Ch, __nv_bfloat16* __restrict__ Cl,
              __nv_bfloat16* __restrict__ C2h, __nv_bfloat16* __restrict__ C2l,
              int M, int N, int K) {
    __shared__ uint32_t Ash[128 * 20], Asl[128 * 20];
    __shared__ uint32_t Bsh[64 * 20],  Bsl[64 * 20];

    const int tid = threadIdx.x;
    const int w = tid >> 5, lane = tid & 31;
    const int g = lane >> 2, l2 = lane & 3;
    const int m0 = blockIdx.y * 128, n0 = blockIdx.x * 64;
    const int mw = (w >> 1) * 64, nw = (w & 1) * 32;
    const int Ku = K >> 1;

    const uint32_t* A32h = (const uint32_t*)Ah;
    const uint32_t* A32l = (const uint32_t*)Al;
    const uint32_t* B32h = (const uint32_t*)Bh;
    const uint32_t* B32l = (const uint32_t*)Bl;

    float acc[4][4][4] = {};

    for (int k0 = 0; k0 < K; k0 += 32) {
        if (k0) __syncthreads();
        {
            int row = tid;
            const uint4* pH = (const uint4*)(A32h + (size_t)(m0 + row) * Ku + (k0 >> 1));
            const uint4* pL = (const uint4*)(A32l + (size_t)(m0 + row) * Ku + (k0 >> 1));
            uint4* dH = (uint4*)&Ash[row * 20];
            uint4* dL = (uint4*)&Asl[row * 20];
#pragma unroll
            for (int e = 0; e < 4; e++) { dH[e] = pH[e]; dL[e] = pL[e]; }
        }
        {
            int row = tid >> 1, hf = tid & 1;
            const uint4* pH = (const uint4*)(B32h + (size_t)(n0 + row) * Ku + (k0 >> 1) + hf * 8);
            const uint4* pL = (const uint4*)(B32l + (size_t)(n0 + row) * Ku + (k0 >> 1) + hf * 8);
            uint4* dH = (uint4*)&Bsh[row * 20 + hf * 8];
            uint4* dL = (uint4*)&Bsl[row * 20 + hf * 8];
#pragma unroll
            for (int e = 0; e < 2; e++) { dH[e] = pH[e]; dL[e] = pL[e]; }
        }
        __syncthreads();

#pragma unroll
        for (int ks = 0; ks < 2; ks++) {
            uint32_t ah[4][4], al[4][4], bh[4][2], bl[4][2];
#pragma unroll
            for (int mt = 0; mt < 4; mt++) {
                int r0 = (mw + mt * 16 + g) * 20 + ks * 8;
                int r1 = (mw + mt * 16 + 8 + g) * 20 + ks * 8;
                ah[mt][0] = Ash[r0 + l2];     ah[mt][1] = Ash[r1 + l2];
                ah[mt][2] = Ash[r0 + 4 + l2]; ah[mt][3] = Ash[r1 + 4 + l2];
                al[mt][0] = Asl[r0 + l2];     al[mt][1] = Asl[r1 + l2];
                al[mt][2] = Asl[r0 + 4 + l2]; al[mt][3] = Asl[r1 + 4 + l2];
            }
#pragma unroll
            for (int nt = 0; nt < 4; nt++) {
                int rb = (nw + nt * 8 + g) * 20 + ks * 8;
                bh[nt][0] = Bsh[rb + l2]; bh[nt][1] = Bsh[rb + 4 + l2];
                bl[nt][0] = Bsl[rb + l2]; bl[nt][1] = Bsl[rb + 4 + l2];
            }
#pragma unroll
            for (int mt = 0; mt < 4; mt++)
#pragma unroll
                for (int nt = 0; nt < 4; nt++) {
                    MMA(acc[mt][nt], ah[mt], bh[nt][0], bh[nt][1]);
                    MMA(acc[mt][nt], ah[mt], bl[nt][0], bl[nt][1]);
                    MMA(acc[mt][nt], al[mt], bh[nt][0], bh[nt][1]);
                }
        }
    }

#pragma unroll
    for (int mt = 0; mt < 4; mt++)
#pragma unroll
        for (int nt = 0; nt < 4; nt++) {
            int row = m0 + mw + mt * 16 + g;
            int col = n0 + nw + nt * 8 + 2 * l2;
            float b0 = bias[col], b1 = bias[col + 1];
            float v0 = acc[mt][nt][0] + b0, v1 = acc[mt][nt][1] + b1;
            float v2 = acc[mt][nt][2] + b0, v3 = acc[mt][nt][3] + b1;
            if (EPI == 1) {
                v0 = 0.5f * v0 * (1.0f + erff(v0 * 0.70710678118654752f));
                v1 = 0.5f * v1 * (1.0f + erff(v1 * 0.70710678118654752f));
                v2 = 0.5f * v2 * (1.0f + erff(v2 * 0.70710678118654752f));
                v3 = 0.5f * v3 * (1.0f + erff(v3 * 0.70710678118654752f));
                uint32_t hi, lo;
                bfsplit2(v0, v1, hi, lo);
                ((uint32_t*)Ch)[((size_t)row * N + col) >> 1] = hi;
                ((uint32_t*)Cl)[((size_t)row * N + col) >> 1] = lo;
                bfsplit2(v2, v3, hi, lo);
                ((uint32_t*)Ch)[((size_t)(row + 8) * N + col) >> 1] = hi;
                ((uint32_t*)Cl)[((size_t)(row + 8) * N + col) >> 1] = lo;
            } else if (EPI == 3) {
                // Q fp32, K -> [h][key][d] hi/lo, V -> [h][d][key] hi/lo
                if (col < 256) {
                    *(float2*)(Cf + (size_t)row * 256 + col) = make_float2(v0, v1);
                    *(float2*)(Cf + (size_t)(row + 8) * 256 + col) = make_float2(v2, v3);
                } else if (col < 512) {
                    int c = col - 256, h = c >> 5, d = c & 31;
                    uint32_t hi, lo;
                    size_t base = ((size_t)h * NTOK) * 16 + (d >> 1);
                    bfsplit2(v0, v1, hi, lo);
                    ((uint32_t*)Ch)[base + (size_t)row * 16] = hi;
                    ((uint32_t*)Cl)[base + (size_t)row * 16] = lo;
                    bfsplit2(v2, v3, hi, lo);
                    ((uint32_t*)Ch)[base + (size_t)(row + 8) * 16] = hi;
                    ((uint32_t*)Cl)[base + (size_t)(row + 8) * 16] = lo;
                } else {
                    int c = col - 512, h = c >> 5, d = c & 31;
                    size_t b0i = ((size_t)h * HDIM + d) * NTOK;
                    size_t b1i = b0i + NTOK;
                    __nv_bfloat16 h0 = __float2bfloat16(v0);
                    __nv_bfloat16 h1 = __float2bfloat16(v1);
                    __nv_bfloat16 h2 = __float2bfloat16(v2);
                    __nv_bfloat16 h3 = __float2bfloat16(v3);
                    C2h[b0i + row] = h0;
                    C2h[b1i + row] = h1;
                    C2h[b0i + row + 8] = h2;
                    C2h[b1i + row + 8] = h3;
                    C2l[b0i + row] = __float2bfloat16(v0 - __bfloat162float(h0));
                    C2l[b1i + row] = __float2bfloat16(v1 - __bfloat162float(h1));
                    C2l[b0i + row + 8] = __float2bfloat16(v2 - __bfloat162float(h2));
                    C2l[b1i + row + 8] = __float2bfloat16(v3 - __bfloat162float(h3));
                }
            } else {
                if (EPI == 2) {
                    const float2 r0 = *(const float2*)(res + (size_t)row * N + col);
                    const float2 r1 = *(const float2*)(res + (size_t)(row + 8) * N + col);
                    v0 += r0.x; v1 += r0.y; v2 += r1.x; v3 += r1.y;
                }
                *(float2*)(Cf + (size_t)row * N + col) = make_float2(v0, v1);
                *(float2*)(Cf + (size_t)(row + 8) * N + col) = make_float2(v2, v3);
            }
        }
}

// ============================ mma.sync attention ===========================
// 128 threads = 4 warps; warp w owns 16 queries. Block = 64 queries.
// grid (NTOK/64, HEADS). K/V already bf16 hi/lo in MMA-friendly layouts:
// staging is pure 16B copies. Padded strides are multiples of 4 u32 so
// STS.128 stays aligned (20 for K rows, 36 for V rows).
__global__ __launch_bounds__(128, 3)
void attn_mma(const float* __restrict__ qf,
              const __nv_bfloat16* __restrict__ KHg, const __nv_bfloat16* __restrict__ KLg,
              const __nv_bfloat16* __restrict__ VHg, const __nv_bfloat16* __restrict__ VLg,
              __nv_bfloat16* __restrict__ att_hi,
              __nv_bfloat16* __restrict__ att_lo) {
    __shared__ uint32_t Khi[64 * 20], Klo[64 * 20];
    __shared__ uint32_t Vhi[32 * 36], Vlo[32 * 36];

    const int t = threadIdx.x;
    const int w = t >> 5;
    const int lane = t & 31;
    const int g = lane >> 2;
    const int l2 = lane & 3;
    const int h = blockIdx.y;
    const int q0 = blockIdx.x * 64;

    // Q fragments (16 queries per warp), scaled by 1/sqrt(d)*log2e
    uint32_t qhi[2][4], qlo[2][4];
    {
        const float qs = 0.17677669529663687f * 1.4426950408889634f;
        const int qrow = q0 + w * 16;
#pragma unroll
        for (int ks = 0; ks < 2; ks++) {
            const float* r0p = qf + (size_t)(qrow + g) * CDIM +
                               h * HDIM + ks * 16 + 2 * l2;
            const float* r1p = r0p + 8 * CDIM;
            float2 v0 = *(const float2*)r0p;
            float2 v1 = *(const float2*)r1p;
            float2 v2 = *(const float2*)(r0p + 8);
            float2 v3 = *(const float2*)(r1p + 8);
            bfsplit2(v0.x * qs, v0.y * qs, qhi[ks][0], qlo[ks][0]);
            bfsplit2(v1.x * qs, v1.y * qs, qhi[ks][1], qlo[ks][1]);
            bfsplit2(v2.x * qs, v2.y * qs, qhi[ks][2], qlo[ks][2]);
            bfsplit2(v3.x * qs, v3.y * qs, qhi[ks][3], qlo[ks][3]);
        }
    }

    float o[4][4];
#pragma unroll
    for (int nt = 0; nt < 4; nt++)
#pragma unroll
        for (int i = 0; i < 4; i++) o[nt][i] = 0.f;
    float m0r = -1e30f, m1r = -1e30f;
    float l0a = 0.f, l1a = 0.f;

    const uint32_t* KH32 = (const uint32_t*)(KHg + (size_t)h * NTOK * HDIM);
    const uint32_t* KL32 = (const uint32_t*)(KLg + (size_t)h * NTOK * HDIM);
    const uint32_t* VH32 = (const uint32_t*)(VHg + (size_t)h * HDIM * NTOK);
    const uint32_t* VL32 = (const uint32_t*)(VLg + (size_t)h * HDIM * NTOK);

    for (int tile = 0; tile < NTOK / 64; tile++) {
        const int key0 = tile * 64;
        if (tile) __syncthreads();

        {   // K: 64 keys x 16 u32, thread -> (key, half)
            int key = t >> 1, hf = t & 1;
            const uint4* pH = (const uint4*)(KH32 + (size_t)(key0 + key) * 16 + hf * 8);
            const uint4* pL = (const uint4*)(KL32 + (size_t)(key0 + key) * 16 + hf * 8);
            uint4* dH = (uint4*)&Khi[key * 20 + hf * 8];
            uint4* dL = (uint4*)&Klo[key * 20 + hf * 8];
            dH[0] = pH[0]; dH[1] = pH[1];
            dL[0] = pL[0]; dL[1] = pL[1];
        }
        {   // V: 32 d-rows x 32 u32, thread -> (d, quarter)
            int d = t >> 2, qd = t & 3;
            const uint4* pH = (const uint4*)(VH32 + (size_t)d * (NTOK / 2) + key0 / 2 + qd * 8);
            const uint4* pL = (const uint4*)(VL32 + (size_t)d * (NTOK / 2) + key0 / 2 + qd * 8);
            uint4* dH = (uint4*)&Vhi[d * 36 + qd * 8];
            uint4* dL = (uint4*)&Vlo[d * 36 + qd * 8];
            dH[0] = pH[0]; dH[1] = pH[1];
            dL[0] = pL[0]; dL[1] = pL[1];
        }
        __syncthreads();

        // S = Q K^T (3-term)
        float s[8][4];
#pragma unroll
        for (int nt = 0; nt < 8; nt++) {
            int key = g + nt * 8;
            const uint32_t* kh = &Khi[key * 20];
            const uint32_t* kl = &Klo[key * 20];
            uint32_t bh00 = kh[l2],     bh01 = kh[4 + l2];
            uint32_t bh10 = kh[8 + l2], bh11 = kh[12 + l2];
            uint32_t bl00 = kl[l2],     bl01 = kl[4 + l2];
            uint32_t bl10 = kl[8 + l2], bl11 = kl[12 + l2];
            float c[4] = {0.f, 0.f, 0.f, 0.f};
            MMA(c, qhi[0], bh00, bh01);
            MMA(c, qhi[1], bh10, bh11);
            MMA(c, qhi[0], bl00, bl01);
            MMA(c, qhi[1], bl10, bl11);
            MMA(c, qlo[0], bh00, bh01);
            MMA(c, qlo[1], bh10, bh11);
            s[nt][0] = c[0]; s[nt][1] = c[1]; s[nt][2] = c[2]; s[nt][3] = c[3];
        }

        // online softmax
        float mx0 = -1e30f, mx1 = -1e30f;
#pragma unroll
        for (int nt = 0; nt < 8; nt++) {
            mx0 = fmaxf(mx0, fmaxf(s[nt][0], s[nt][1]));
            mx1 = fmaxf(mx1, fmaxf(s[nt][2], s[nt][3]));
        }
        mx0 = fmaxf(mx0, __shfl_xor_sync(0xFFFFFFFFu, mx0, 1));
        mx0 = fmaxf(mx0, __shfl_xor_sync(0xFFFFFFFFu, mx0, 2));
        mx1 = fmaxf(mx1, __shfl_xor_sync(0xFFFFFFFFu, mx1, 1));
        mx1 = fmaxf(mx1, __shfl_xor_sync(0xFFFFFFFFu, mx1, 2));
        float mn0 = fmaxf(m0r, mx0);
        float mn1 = fmaxf(m1r, mx1);
        float cr0 = exp2_fast(m0r - mn0);
        float cr1 = exp2_fast(m1r - mn1);
        m0r = mn0; m1r = mn1;
        l0a *= cr0; l1a *= cr1;
#pragma unroll
        for (int nt = 0; nt < 4; nt++) {
            o[nt][0] *= cr0; o[nt][1] *= cr0;
            o[nt][2] *= cr1; o[nt][3] *= cr1;
        }

        uint32_t phi[4][4], plo[4][4];
        float s0 = 0.f, s1 = 0.f;
#pragma unroll
        for (int nt = 0; nt < 8; nt++) {
            float p0 = exp2_fast(s[nt][0] - mn0);
            float p1 = exp2_fast(s[nt][1] - mn0);
            float p2 = exp2_fast(s[nt][2] - mn1);
            float p3 = exp2_fast(s[nt][3] - mn1);
            s0 += p0 + p1; s1 += p2 + p3;
            int kv = nt >> 1, hf = (nt & 1) * 2;
            uint16_t h0 = bf16_rn(p0), h1 = bf16_rn(p1);
            uint16_t h2 = bf16_rn(p2), h3 = bf16_rn(p3);
            phi[kv][hf]     = pack2(h0, h1);
            phi[kv][hf + 1] = pack2(h2, h3);
            plo[kv][hf]     = pack2(bf16_rn(p0 - bf16f(h0)),
                                    bf16_rn(p1 - bf16f(h1)));
            plo[kv][hf + 1] = pack2(bf16_rn(p2 - bf16f(h2)),
                                    bf16_rn(p3 - bf16f(h3)));
        }
        l0a += s0; l1a += s1;

        // O += P V (3-term)
#pragma unroll
        for (int nt = 0; nt < 4; nt++) {
            int n = g + nt * 8;
            const uint32_t* vh = &Vhi[n * 36];
            const uint32_t* vl = &Vlo[n * 36];
#pragma unroll
            for (int kv = 0; kv < 4; kv++) {
                uint32_t vh0 = vh[kv * 8 + l2], vh1 = vh[kv * 8 + 4 + l2];
                uint32_t vl0 = vl[kv * 8 + l2], vl1 = vl[kv * 8 + 4 + l2];
                MMA(o[nt], phi[kv], vh0, vh1);
                MMA(o[nt], phi[kv], vl0, vl1);
                MMA(o[nt], plo[kv], vh0, vh1);
            }
        }
    }

    // normalize + write bf16 hi/lo
    float l0 = l0a;
    l0 += __shfl_xor_sync(0xFFFFFFFFu, l0, 1);
    l0 += __shfl_xor_sync(0xFFFFFFFFu, l0, 2);
    float l1 = l1a;
    l1 += __shfl_xor_sync(0xFFFFFFFFu, l1, 1);
    l1 += __shfl_xor_sync(0xFFFFFFFFu, l1, 2);
    float i0 = 1.0f / l0, i1 = 1.0f / l1;
    int r0 = q0 + w * 16 + g;
#pragma unroll
    for (int nt = 0; nt < 4; nt++) {
        int col = h * HDIM + nt * 8 + 2 * l2;
        uint32_t hi, lo;
        bfsplit2(o[nt][0] * i0, o[nt][1] * i0, hi, lo);
        ((uint32_t*)att_hi)[((size_t)r0 * CDIM + col) >> 1] = hi;
        ((uint32_t*)att_lo)[((size_t)r0 * CDIM + col) >> 1] = lo;
        bfsplit2(o[nt][2] * i1, o[nt][3] * i1, hi, lo);
        ((uint32_t*)att_hi)[((size_t)(r0 + 8) * CDIM + col) >> 1] = hi;
        ((uint32_t*)att_lo)[((size_t)(r0 + 8) * CDIM + col) >> 1] = lo;
    }
}

// ============================ launch =======================================
extern "C" void kernel_launch(void* const* d_in, const int* in_sizes, int n_in,
                              void* d_out, int out_size) {
    const float* x      = (const float*)d_in[0];
    const float* ln1_g  = (const float*)d_in[1];
    const float* ln1_b  = (const float*)d_in[2];
    const float* w_qkv  = (const float*)d_in[3];
    const float* b_qkv  = (const float*)d_in[4];
    const float* w_proj = (const float*)d_in[5];
    const float* b_proj = (const float*)d_in[6];
    const float* ln2_g  = (const float*)d_in[7];
    const float* ln2_b  = (const float*)d_in[8];
    const float* w_mlp1 = (const float*)d_in[9];
    const float* b_mlp1 = (const float*)d_in[10];
    const float* w_mlp2 = (const float*)d_in[11];
    const float* b_mlp2 = (const float*)d_in[12];
    float* out = (float*)d_out;

    float *xl, *qfp;
    __nv_bfloat16 *kh, *kl, *vh2, *vl2;
    __nv_bfloat16 *xnh, *xnl, *atth, *attl, *h1h, *h1l, *wh, *wl;
    cudaGetSymbolAddress((void**)&xl,   g_xl);
    cudaGetSymbolAddress((void**)&qfp,  g_qf);
    cudaGetSymbolAddress((void**)&kh,   g_kh);
    cudaGetSymbolAddress((void**)&kl,   g_kl);
    cudaGetSymbolAddress((void**)&vh2,  g_vh);
    cudaGetSymbolAddress((void**)&vl2,  g_vl);
    cudaGetSymbolAddress((void**)&xnh,  g_xn_hi);
    cudaGetSymbolAddress((void**)&xnl,  g_xn_lo);
    cudaGetSymbolAddress((void**)&atth, g_att_hi);
    cudaGetSymbolAddress((void**)&attl, g_att_lo);
    cudaGetSymbolAddress((void**)&h1h,  g_h1_hi);
    cudaGetSymbolAddress((void**)&h1l,  g_h1_lo);
    cudaGetSymbolAddress((void**)&wh,   g_w_hi);
    cudaGetSymbolAddress((void**)&wl,   g_w_lo);

    dim3 tb(32, 8);

    wsplit_k<<<(768 * 256 + 255) / 256, 256>>>(w_qkv,  wh + WOFF_QKV,  wl + WOFF_QKV,  768 * 256);
    wsplit_k<<<(256 * 256 + 255) / 256, 256>>>(w_proj, wh + WOFF_PROJ, wl + WOFF_PROJ, 256 * 256);
    wsplit_k<<<(1024 * 256 + 255) / 256, 256>>>(w_mlp1, wh + WOFF_MLP1, wl + WOFF_MLP1, 1024 * 256);
    wsplit_k<<<(256 * 1024 + 255) / 256, 256>>>(w_mlp2, wh + WOFF_MLP2, wl + WOFF_MLP2, 256 * 1024);

    transpose_k<<<dim3(NTOK / 32, CDIM / 32), tb>>>(x, xl, CDIM, NTOK);
    ln_kernel<<<NTOK, CDIM>>>(xl, ln1_g, ln1_b, xnh, xnl);

    // QKV GEMM with scatter epilogue: Q fp32, K/V bf16 hi/lo pre-laid-out
    hgemm_tn<3><<<dim3(768 / 64, NTOK / 128), 128>>>(
        xnh, xnl, wh + WOFF_QKV, wl + WOFF_QKV, b_qkv, nullptr,
        qfp, kh, kl, vh2, vl2, NTOK, 768, CDIM);

    attn_mma<<<dim3(NTOK / 64, HEADS), 128>>>(qfp, kh, kl, vh2, vl2, atth, attl);

    hgemm_tn<2><<<dim3(CDIM / 64, NTOK / 128), 128>>>(
        atth, attl, wh + WOFF_PROJ, wl + WOFF_PROJ, b_proj, xl,
        xl, nullptr, nullptr, nullptr, nullptr, NTOK, CDIM, CDIM);

    ln_kernel<<<NTOK, CDIM>>>(xl, ln2_g, ln2_b, xnh, xnl);

    hgemm_tn<1><<<dim3(1024 / 64, NTOK / 128), 128>>>(
        xnh, xnl, wh + WOFF_MLP1, wl + WOFF_MLP1, b_mlp1, nullptr,
        nullptr, h1h, h1l, nullptr, nullptr, NTOK, 1024, CDIM);

    hgemm_tn<2><<<dim3(CDIM / 64, NTOK / 128), 128>>>(
        h1h, h1l, wh + WOFF_MLP2, wl + WOFF_MLP2, b_mlp2, xl,
        xl, nullptr, nullptr, nullptr, nullptr, NTOK, CDIM, 4 * CDIM);

    transpose_k<<<dim3(CDIM / 32, NTOK / 32), tb>>>(xl, out, NTOK, CDIM);
}

// round 8
// speedup vs baseline: 1.0878x; 1.0878x over previous
#include <cuda_runtime.h>
#include <cuda_bf16.h>
#include <math.h>
#include <stdint.h>

// ---------------------------------------------------------------------------
// TransformerBlock: x[1,256,64,64]. N=4096 tokens, C=256, 8 heads, d=32.
// Attention + all GEMMs on mma.sync bf16 3-term (fp32-accurate).
// K/V split/transposed by a dedicated coalesced converter kernel.
// ---------------------------------------------------------------------------

#define NTOK 4096
#define CDIM 256
#define HEADS 8
#define HDIM 32

__device__ float g_xl[NTOK * CDIM];
__device__ float g_qkv[NTOK * 3 * CDIM];
__device__ __nv_bfloat16 g_kh[HEADS * NTOK * HDIM];      // K hi [h][key][d]
__device__ __nv_bfloat16 g_kl[HEADS * NTOK * HDIM];
__device__ __nv_bfloat16 g_vh[HEADS * HDIM * NTOK];      // V hi [h][d][key]
__device__ __nv_bfloat16 g_vl[HEADS * HDIM * NTOK];
__device__ __nv_bfloat16 g_xn_hi[NTOK * CDIM],  g_xn_lo[NTOK * CDIM];
__device__ __nv_bfloat16 g_att_hi[NTOK * CDIM], g_att_lo[NTOK * CDIM];
__device__ __nv_bfloat16 g_h1_hi[NTOK * 4 * CDIM], g_h1_lo[NTOK * 4 * CDIM];
#define WOFF_QKV  0
#define WOFF_PROJ 196608
#define WOFF_MLP1 262144
#define WOFF_MLP2 524288
__device__ __nv_bfloat16 g_w_hi[786432], g_w_lo[786432];

// ============================ helpers ======================================
__device__ __forceinline__ uint16_t bf16_rn(float x) {
    __nv_bfloat16 h = __float2bfloat16(x);
    return *reinterpret_cast<uint16_t*>(&h);
}
__device__ __forceinline__ float bf16f(uint16_t u) {
    return __uint_as_float((uint32_t)u << 16);
}
__device__ __forceinline__ uint32_t pack2(uint16_t lo, uint16_t hi) {
    return (uint32_t)lo | ((uint32_t)hi << 16);
}
__device__ __forceinline__ void bfsplit2(float x, float y,
                                         uint32_t& hi, uint32_t& lo) {
    uint16_t hx = bf16_rn(x), hy = bf16_rn(y);
    hi = pack2(hx, hy);
    lo = pack2(bf16_rn(x - bf16f(hx)), bf16_rn(y - bf16f(hy)));
}

#define MMA(c, a, b0, b1)                                                      \
    asm volatile("mma.sync.aligned.m16n8k16.row.col.f32.bf16.bf16.f32 "        \
        "{%0,%1,%2,%3}, {%4,%5,%6,%7}, {%8,%9}, {%0,%1,%2,%3};"                \
        : "+f"((c)[0]), "+f"((c)[1]), "+f"((c)[2]), "+f"((c)[3])               \
        : "r"((a)[0]), "r"((a)[1]), "r"((a)[2]), "r"((a)[3]),                  \
          "r"(b0), "r"(b1))

__device__ __forceinline__ float exp2_fast(float y) {
    y = fmaxf(y, -126.0f);
    int ni = __float2int_rn(y);
    float f = y - (float)ni;
    float p = 1.5403530e-4f;
    p = fmaf(p, f, 1.33335581e-3f);
    p = fmaf(p, f, 9.61812911e-3f);
    p = fmaf(p, f, 5.55041087e-2f);
    p = fmaf(p, f, 2.40226507e-1f);
    p = fmaf(p, f, 6.93147181e-1f);
    p = fmaf(p, f, 1.0f);
    float sc = __int_as_float((ni + 127) << 23);
    return p * sc;
}

// ============================ small kernels ================================
__global__ void transpose_k(const float* __restrict__ src, float* __restrict__ dst,
                            int R, int C) {
    __shared__ float tile[32][33];
    int c0 = blockIdx.x * 32, r0 = blockIdx.y * 32;
    int x = threadIdx.x, y = threadIdx.y;
#pragma unroll
    for (int i = y; i < 32; i += 8)
        tile[i][x] = src[(size_t)(r0 + i) * C + c0 + x];
    __syncthreads();
#pragma unroll
    for (int i = y; i < 32; i += 8)
        dst[(size_t)(c0 + i) * R + r0 + x] = tile[x][i];
}

__global__ void wsplit_k(const float* __restrict__ src,
                         __nv_bfloat16* __restrict__ hi,
                         __nv_bfloat16* __restrict__ lo, int n) {
    int i = blockIdx.x * 256 + threadIdx.x;
    if (i < n) {
        float v = src[i];
        __nv_bfloat16 h = __float2bfloat16(v);
        hi[i] = h;
        lo[i] = __float2bfloat16(v - __bfloat162float(h));
    }
}

__global__ void ln_kernel(const float* __restrict__ in, const float* __restrict__ g,
                          const float* __restrict__ b,
                          __nv_bfloat16* __restrict__ ohi,
                          __nv_bfloat16* __restrict__ olo) {
    int n = blockIdx.x;
    int c = threadIdx.x;
    float v = in[n * CDIM + c];
    float s1 = v, s2 = v * v;
#pragma unroll
    for (int off = 16; off > 0; off >>= 1) {
        s1 += __shfl_xor_sync(0xFFFFFFFFu, s1, off);
        s2 += __shfl_xor_sync(0xFFFFFFFFu, s2, off);
    }
    __shared__ float sh1[8], sh2[8];
    int w = c >> 5, lane = c & 31;
    if (lane == 0) { sh1[w] = s1; sh2[w] = s2; }
    __syncthreads();
    float m1 = 0.f, m2 = 0.f;
#pragma unroll
    for (int i = 0; i < 8; i++) { m1 += sh1[i]; m2 += sh2[i]; }
    float mu = m1 * (1.f / CDIM);
    float var = m2 * (1.f / CDIM) - mu * mu;
    float rs = rsqrtf(var + 1e-5f);
    float y = (v - mu) * rs * g[c] + b[c];
    __nv_bfloat16 h = __float2bfloat16(y);
    ohi[n * CDIM + c] = h;
    olo[n * CDIM + c] = __float2bfloat16(y - __bfloat162float(h));
}

// ---------------------------------------------------------------------------
// K/V converter. grid (NTOK/64, HEADS), 256 threads.
// K: qkv[n][256 + h*32 + d] -> kh/kl [h][n][d]    (coalesced both sides)
// V: qkv[n][512 + h*32 + d] -> vh/vl [h][d][n]    (SMEM tile transpose)
// ---------------------------------------------------------------------------
__global__ __launch_bounds__(256)
void kvsplit_k(const float* __restrict__ qkv,
               __nv_bfloat16* __restrict__ KH, __nv_bfloat16* __restrict__ KL,
               __nv_bfloat16* __restrict__ VH, __nv_bfloat16* __restrict__ VL) {
    __shared__ float vt[32][65];   // vt[d][key]
    const int t = threadIdx.x;
    const int key0 = blockIdx.x * 64;
    const int h = blockIdx.y;

    // ---- K: thread -> (key, seg of 8 d) ----
    {
        int key = t >> 2, seg = t & 3;
        const float* kp = qkv + (size_t)(key0 + key) * 768 + 256 + h * HDIM + seg * 8;
        float4 a = ((const float4*)kp)[0];
        float4 b = ((const float4*)kp)[1];
        uint32_t o[8];
        bfsplit2(a.x, a.y, o[0], o[4]);
        bfsplit2(a.z, a.w, o[1], o[5]);
        bfsplit2(b.x, b.y, o[2], o[6]);
        bfsplit2(b.z, b.w, o[3], o[7]);
        size_t idx = (((size_t)h * NTOK + key0 + key) * HDIM + seg * 8) >> 1;
        uint4* dh = (uint4*)((uint32_t*)KH + idx);
        uint4* dl = (uint4*)((uint32_t*)KL + idx);
        dh[0] = make_uint4(o[0], o[1], o[2], o[3]);
        dl[0] = make_uint4(o[4], o[5], o[6], o[7]);
    }

    // ---- V: read coalesced into SMEM transposed, write d-rows ----
    {
        int key = t >> 2, seg = t & 3;
        const float* vp = qkv + (size_t)(key0 + key) * 768 + 512 + h * HDIM + seg * 8;
        float4 a = ((const float4*)vp)[0];
        float4 b = ((const float4*)vp)[1];
        float vals[8] = {a.x, a.y, a.z, a.w, b.x, b.y, b.z, b.w};
#pragma unroll
        for (int j = 0; j < 8; j++) vt[seg * 8 + j][key] = vals[j];
    }
    __syncthreads();
    {
        int d = t >> 3, kseg = t & 7;   // 8 keys per thread
        uint32_t oh[4], ol[4];
#pragma unroll
        for (int j = 0; j < 4; j++) {
            float x = vt[d][kseg * 8 + 2 * j];
            float y = vt[d][kseg * 8 + 2 * j + 1];
            bfsplit2(x, y, oh[j], ol[j]);
        }
        size_t idx = (((size_t)h * HDIM + d) * NTOK + key0 + kseg * 8) >> 1;
        ((uint4*)((uint32_t*)VH + idx))[0] = make_uint4(oh[0], oh[1], oh[2], oh[3]);
        ((uint4*)((uint32_t*)VL + idx))[0] = make_uint4(ol[0], ol[1], ol[2], ol[3]);
    }
}

// ============================ bf16 3-term GEMM =============================
// EPI: 0 fp32 C; 1 GELU -> bf16 hi/lo; 2 +res fp32.
template <int EPI>
__global__ __launch_bounds__(128)
void hgemm_tn(const __nv_bfloat16* __restrict__ Ah, const __nv_bfloat16* __restrict__ Al,
              const __nv_bfloat16* __restrict__ Bh, const __nv_bfloat16* __restrict__ Bl,
              const float* __restrict__ bias, const float* __restrict__ res,
              float* __restrict__ Cf,
              __nv_bfloat16* __restrict__ Ch, __nv_bfloat16* __restrict__ Cl,
              int M, int N, int K) {
    __shared__ uint32_t Ash[128 * 20], Asl[128 * 20];
    __shared__ uint32_t Bsh[64 * 20],  Bsl[64 * 20];

    const int tid = threadIdx.x;
    const int w = tid >> 5, lane = tid & 31;
    const int g = lane >> 2, l2 = lane & 3;
    const int m0 = blockIdx.y * 128, n0 = blockIdx.x * 64;
    const int mw = (w >> 1) * 64, nw = (w & 1) * 32;
    const int Ku = K >> 1;

    const uint32_t* A32h = (const uint32_t*)Ah;
    const uint32_t* A32l = (const uint32_t*)Al;
    const uint32_t* B32h = (const uint32_t*)Bh;
    const uint32_t* B32l = (const uint32_t*)Bl;

    float acc[4][4][4] = {};

    for (int k0 = 0; k0 < K; k0 += 32) {
        if (k0) __syncthreads();
        {
            int row = tid;
            const uint4* pH = (const uint4*)(A32h + (size_t)(m0 + row) * Ku + (k0 >> 1));
            const uint4* pL = (const uint4*)(A32l + (size_t)(m0 + row) * Ku + (k0 >> 1));
            uint4* dH = (uint4*)&Ash[row * 20];
            uint4* dL = (uint4*)&Asl[row * 20];
#pragma unroll
            for (int e = 0; e < 4; e++) { dH[e] = pH[e]; dL[e] = pL[e]; }
        }
        {
            int row = tid >> 1, hf = tid & 1;
            const uint4* pH = (const uint4*)(B32h + (size_t)(n0 + row) * Ku + (k0 >> 1) + hf * 8);
            const uint4* pL = (const uint4*)(B32l + (size_t)(n0 + row) * Ku + (k0 >> 1) + hf * 8);
            uint4* dH = (uint4*)&Bsh[row * 20 + hf * 8];
            uint4* dL = (uint4*)&Bsl[row * 20 + hf * 8];
#pragma unroll
            for (int e = 0; e < 2; e++) { dH[e] = pH[e]; dL[e] = pL[e]; }
        }
        __syncthreads();

#pragma unroll
        for (int ks = 0; ks < 2; ks++) {
            uint32_t ah[4][4], al[4][4], bh[4][2], bl[4][2];
#pragma unroll
            for (int mt = 0; mt < 4; mt++) {
                int r0 = (mw + mt * 16 + g) * 20 + ks * 8;
                int r1 = (mw + mt * 16 + 8 + g) * 20 + ks * 8;
                ah[mt][0] = Ash[r0 + l2];     ah[mt][1] = Ash[r1 + l2];
                ah[mt][2] = Ash[r0 + 4 + l2]; ah[mt][3] = Ash[r1 + 4 + l2];
                al[mt][0] = Asl[r0 + l2];     al[mt][1] = Asl[r1 + l2];
                al[mt][2] = Asl[r0 + 4 + l2]; al[mt][3] = Asl[r1 + 4 + l2];
            }
#pragma unroll
            for (int nt = 0; nt < 4; nt++) {
                int rb = (nw + nt * 8 + g) * 20 + ks * 8;
                bh[nt][0] = Bsh[rb + l2]; bh[nt][1] = Bsh[rb + 4 + l2];
                bl[nt][0] = Bsl[rb + l2]; bl[nt][1] = Bsl[rb + 4 + l2];
            }
#pragma unroll
            for (int mt = 0; mt < 4; mt++)
#pragma unroll
                for (int nt = 0; nt < 4; nt++) {
                    MMA(acc[mt][nt], ah[mt], bh[nt][0], bh[nt][1]);
                    MMA(acc[mt][nt], ah[mt], bl[nt][0], bl[nt][1]);
                    MMA(acc[mt][nt], al[mt], bh[nt][0], bh[nt][1]);
                }
        }
    }

#pragma unroll
    for (int mt = 0; mt < 4; mt++)
#pragma unroll
        for (int nt = 0; nt < 4; nt++) {
            int row = m0 + mw + mt * 16 + g;
            int col = n0 + nw + nt * 8 + 2 * l2;
            float b0 = bias[col], b1 = bias[col + 1];
            float v0 = acc[mt][nt][0] + b0, v1 = acc[mt][nt][1] + b1;
            float v2 = acc[mt][nt][2] + b0, v3 = acc[mt][nt][3] + b1;
            if (EPI == 1) {
                v0 = 0.5f * v0 * (1.0f + erff(v0 * 0.70710678118654752f));
                v1 = 0.5f * v1 * (1.0f + erff(v1 * 0.70710678118654752f));
                v2 = 0.5f * v2 * (1.0f + erff(v2 * 0.70710678118654752f));
                v3 = 0.5f * v3 * (1.0f + erff(v3 * 0.70710678118654752f));
                uint32_t hi, lo;
                bfsplit2(v0, v1, hi, lo);
                ((uint32_t*)Ch)[((size_t)row * N + col) >> 1] = hi;
                ((uint32_t*)Cl)[((size_t)row * N + col) >> 1] = lo;
                bfsplit2(v2, v3, hi, lo);
                ((uint32_t*)Ch)[((size_t)(row + 8) * N + col) >> 1] = hi;
                ((uint32_t*)Cl)[((size_t)(row + 8) * N + col) >> 1] = lo;
            } else {
                if (EPI == 2) {
                    const float2 r0 = *(const float2*)(res + (size_t)row * N + col);
                    const float2 r1 = *(const float2*)(res + (size_t)(row + 8) * N + col);
                    v0 += r0.x; v1 += r0.y; v2 += r1.x; v3 += r1.y;
                }
                *(float2*)(Cf + (size_t)row * N + col) = make_float2(v0, v1);
                *(float2*)(Cf + (size_t)(row + 8) * N + col) = make_float2(v2, v3);
            }
        }
}

// ============================ mma.sync attention ===========================
// 128 threads = 4 warps; warp w owns 32 queries. Block = 128 queries.
// grid (NTOK/128, HEADS). K/V pre-split bf16 hi/lo: staging = 16B copies.
__global__ __launch_bounds__(128)
void attn_mma(const float* __restrict__ qkv,
              const __nv_bfloat16* __restrict__ KHg, const __nv_bfloat16* __restrict__ KLg,
              const __nv_bfloat16* __restrict__ VHg, const __nv_bfloat16* __restrict__ VLg,
              __nv_bfloat16* __restrict__ att_hi,
              __nv_bfloat16* __restrict__ att_lo) {
    __shared__ uint32_t Khi[64 * 20], Klo[64 * 20];
    __shared__ uint32_t Vhi[32 * 36], Vlo[32 * 36];

    const int t = threadIdx.x;
    const int w = t >> 5;
    const int lane = t & 31;
    const int g = lane >> 2;
    const int l2 = lane & 3;
    const int h = blockIdx.y;
    const int q0 = blockIdx.x * 128;

    // Q fragments (32 queries per warp), scaled by 1/sqrt(d)*log2e
    uint32_t qhi[2][2][4], qlo[2][2][4];
    {
        const float qs = 0.17677669529663687f * 1.4426950408889634f;
        const int qrow = q0 + w * 32;
#pragma unroll
        for (int mt = 0; mt < 2; mt++)
#pragma unroll
        for (int ks = 0; ks < 2; ks++) {
            const float* r0p = qkv + (size_t)(qrow + mt * 16 + g) * 768 +
                               h * HDIM + ks * 16 + 2 * l2;
            const float* r1p = r0p + 8 * 768;
            float2 v0 = *(const float2*)r0p;
            float2 v1 = *(const float2*)r1p;
            float2 v2 = *(const float2*)(r0p + 8);
            float2 v3 = *(const float2*)(r1p + 8);
            bfsplit2(v0.x * qs, v0.y * qs, qhi[mt][ks][0], qlo[mt][ks][0]);
            bfsplit2(v1.x * qs, v1.y * qs, qhi[mt][ks][1], qlo[mt][ks][1]);
            bfsplit2(v2.x * qs, v2.y * qs, qhi[mt][ks][2], qlo[mt][ks][2]);
            bfsplit2(v3.x * qs, v3.y * qs, qhi[mt][ks][3], qlo[mt][ks][3]);
        }
    }

    float o[2][4][4];
#pragma unroll
    for (int mt = 0; mt < 2; mt++)
#pragma unroll
        for (int nt = 0; nt < 4; nt++)
#pragma unroll
            for (int i = 0; i < 4; i++) o[mt][nt][i] = 0.f;
    float mrow[2][2] = {{-1e30f, -1e30f}, {-1e30f, -1e30f}};
    float lacc[2][2] = {{0.f, 0.f}, {0.f, 0.f}};

    const uint32_t* KH32 = (const uint32_t*)(KHg + (size_t)h * NTOK * HDIM);
    const uint32_t* KL32 = (const uint32_t*)(KLg + (size_t)h * NTOK * HDIM);
    const uint32_t* VH32 = (const uint32_t*)(VHg + (size_t)h * HDIM * NTOK);
    const uint32_t* VL32 = (const uint32_t*)(VLg + (size_t)h * HDIM * NTOK);

    for (int tile = 0; tile < NTOK / 64; tile++) {
        const int key0 = tile * 64;
        if (tile) __syncthreads();

        {   // K: 64 keys x 16 u32, thread -> (key, half)
            int key = t >> 1, hf = t & 1;
            const uint4* pH = (const uint4*)(KH32 + (size_t)(key0 + key) * 16 + hf * 8);
            const uint4* pL = (const uint4*)(KL32 + (size_t)(key0 + key) * 16 + hf * 8);
            uint4* dH = (uint4*)&Khi[key * 20 + hf * 8];
            uint4* dL = (uint4*)&Klo[key * 20 + hf * 8];
            dH[0] = pH[0]; dH[1] = pH[1];
            dL[0] = pL[0]; dL[1] = pL[1];
        }
        {   // V: 32 d-rows x 32 u32, thread -> (d, quarter)
            int d = t >> 2, qd = t & 3;
            const uint4* pH = (const uint4*)(VH32 + (size_t)d * (NTOK / 2) + key0 / 2 + qd * 8);
            const uint4* pL = (const uint4*)(VL32 + (size_t)d * (NTOK / 2) + key0 / 2 + qd * 8);
            uint4* dH = (uint4*)&Vhi[d * 36 + qd * 8];
            uint4* dL = (uint4*)&Vlo[d * 36 + qd * 8];
            dH[0] = pH[0]; dH[1] = pH[1];
            dL[0] = pL[0]; dL[1] = pL[1];
        }
        __syncthreads();

#pragma unroll
        for (int mt = 0; mt < 2; mt++) {
            // S = Q K^T (3-term)
            float s[8][4];
#pragma unroll
            for (int nt = 0; nt < 8; nt++) {
                int key = g + nt * 8;
                const uint32_t* kh = &Khi[key * 20];
                const uint32_t* kl = &Klo[key * 20];
                uint32_t bh00 = kh[l2],     bh01 = kh[4 + l2];
                uint32_t bh10 = kh[8 + l2], bh11 = kh[12 + l2];
                uint32_t bl00 = kl[l2],     bl01 = kl[4 + l2];
                uint32_t bl10 = kl[8 + l2], bl11 = kl[12 + l2];
                float c[4] = {0.f, 0.f, 0.f, 0.f};
                MMA(c, qhi[mt][0], bh00, bh01);
                MMA(c, qhi[mt][1], bh10, bh11);
                MMA(c, qhi[mt][0], bl00, bl01);
                MMA(c, qhi[mt][1], bl10, bl11);
                MMA(c, qlo[mt][0], bh00, bh01);
                MMA(c, qlo[mt][1], bh10, bh11);
                s[nt][0] = c[0]; s[nt][1] = c[1]; s[nt][2] = c[2]; s[nt][3] = c[3];
            }

            // online softmax
            float mx0 = -1e30f, mx1 = -1e30f;
#pragma unroll
            for (int nt = 0; nt < 8; nt++) {
                mx0 = fmaxf(mx0, fmaxf(s[nt][0], s[nt][1]));
                mx1 = fmaxf(mx1, fmaxf(s[nt][2], s[nt][3]));
            }
            mx0 = fmaxf(mx0, __shfl_xor_sync(0xFFFFFFFFu, mx0, 1));
            mx0 = fmaxf(mx0, __shfl_xor_sync(0xFFFFFFFFu, mx0, 2));
            mx1 = fmaxf(mx1, __shfl_xor_sync(0xFFFFFFFFu, mx1, 1));
            mx1 = fmaxf(mx1, __shfl_xor_sync(0xFFFFFFFFu, mx1, 2));
            float mn0 = fmaxf(mrow[mt][0], mx0);
            float mn1 = fmaxf(mrow[mt][1], mx1);
            float cr0 = exp2_fast(mrow[mt][0] - mn0);
            float cr1 = exp2_fast(mrow[mt][1] - mn1);
            mrow[mt][0] = mn0; mrow[mt][1] = mn1;
            lacc[mt][0] *= cr0; lacc[mt][1] *= cr1;
#pragma unroll
            for (int nt4 = 0; nt4 < 4; nt4++) {
                o[mt][nt4][0] *= cr0; o[mt][nt4][1] *= cr0;
                o[mt][nt4][2] *= cr1; o[mt][nt4][3] *= cr1;
            }

            uint32_t phi[4][4], plo[4][4];
            float s0 = 0.f, s1 = 0.f;
#pragma unroll
            for (int nt = 0; nt < 8; nt++) {
                float p0 = exp2_fast(s[nt][0] - mn0);
                float p1 = exp2_fast(s[nt][1] - mn0);
                float p2 = exp2_fast(s[nt][2] - mn1);
                float p3 = exp2_fast(s[nt][3] - mn1);
                s0 += p0 + p1; s1 += p2 + p3;
                int kv = nt >> 1, hf = (nt & 1) * 2;
                uint16_t h0 = bf16_rn(p0), h1 = bf16_rn(p1);
                uint16_t h2 = bf16_rn(p2), h3 = bf16_rn(p3);
                phi[kv][hf]     = pack2(h0, h1);
                phi[kv][hf + 1] = pack2(h2, h3);
                plo[kv][hf]     = pack2(bf16_rn(p0 - bf16f(h0)),
                                        bf16_rn(p1 - bf16f(h1)));
                plo[kv][hf + 1] = pack2(bf16_rn(p2 - bf16f(h2)),
                                        bf16_rn(p3 - bf16f(h3)));
            }
            lacc[mt][0] += s0; lacc[mt][1] += s1;

            // O += P V (3-term)
#pragma unroll
            for (int nt4 = 0; nt4 < 4; nt4++) {
                int n = g + nt4 * 8;
                const uint32_t* vh = &Vhi[n * 36];
                const uint32_t* vl = &Vlo[n * 36];
#pragma unroll
                for (int kv = 0; kv < 4; kv++) {
                    uint32_t vh0 = vh[kv * 8 + l2], vh1 = vh[kv * 8 + 4 + l2];
                    uint32_t vl0 = vl[kv * 8 + l2], vl1 = vl[kv * 8 + 4 + l2];
                    MMA(o[mt][nt4], phi[kv], vh0, vh1);
                    MMA(o[mt][nt4], phi[kv], vl0, vl1);
                    MMA(o[mt][nt4], plo[kv], vh0, vh1);
                }
            }
        }
    }

    // normalize + write bf16 hi/lo
#pragma unroll
    for (int mt = 0; mt < 2; mt++) {
        float l0 = lacc[mt][0];
        l0 += __shfl_xor_sync(0xFFFFFFFFu, l0, 1);
        l0 += __shfl_xor_sync(0xFFFFFFFFu, l0, 2);
        float l1 = lacc[mt][1];
        l1 += __shfl_xor_sync(0xFFFFFFFFu, l1, 1);
        l1 += __shfl_xor_sync(0xFFFFFFFFu, l1, 2);
        float i0 = 1.0f / l0, i1 = 1.0f / l1;
        int r0 = q0 + w * 32 + mt * 16 + g;
#pragma unroll
        for (int nt4 = 0; nt4 < 4; nt4++) {
            int col = h * HDIM + nt4 * 8 + 2 * l2;
            uint32_t hi, lo;
            bfsplit2(o[mt][nt4][0] * i0, o[mt][nt4][1] * i0, hi, lo);
            ((uint32_t*)att_hi)[((size_t)r0 * CDIM + col) >> 1] = hi;
            ((uint32_t*)att_lo)[((size_t)r0 * CDIM + col) >> 1] = lo;
            bfsplit2(o[mt][nt4][2] * i1, o[mt][nt4][3] * i1, hi, lo);
            ((uint32_t*)att_hi)[((size_t)(r0 + 8) * CDIM + col) >> 1] = hi;
            ((uint32_t*)att_lo)[((size_t)(r0 + 8) * CDIM + col) >> 1] = lo;
        }
    }
}

// ============================ launch =======================================
extern "C" void kernel_launch(void* const* d_in, const int* in_sizes, int n_in,
                              void* d_out, int out_size) {
    const float* x      = (const float*)d_in[0];
    const float* ln1_g  = (const float*)d_in[1];
    const float* ln1_b  = (const float*)d_in[2];
    const float* w_qkv  = (const float*)d_in[3];
    const float* b_qkv  = (const float*)d_in[4];
    const float* w_proj = (const float*)d_in[5];
    const float* b_proj = (const float*)d_in[6];
    const float* ln2_g  = (const float*)d_in[7];
    const float* ln2_b  = (const float*)d_in[8];
    const float* w_mlp1 = (const float*)d_in[9];
    const float* b_mlp1 = (const float*)d_in[10];
    const float* w_mlp2 = (const float*)d_in[11];
    const float* b_mlp2 = (const float*)d_in[12];
    float* out = (float*)d_out;

    float *xl, *qkv;
    __nv_bfloat16 *kh, *kl, *vh2, *vl2;
    __nv_bfloat16 *xnh, *xnl, *atth, *attl, *h1h, *h1l, *wh, *wl;
    cudaGetSymbolAddress((void**)&xl,   g_xl);
    cudaGetSymbolAddress((void**)&qkv,  g_qkv);
    cudaGetSymbolAddress((void**)&kh,   g_kh);
    cudaGetSymbolAddress((void**)&kl,   g_kl);
    cudaGetSymbolAddress((void**)&vh2,  g_vh);
    cudaGetSymbolAddress((void**)&vl2,  g_vl);
    cudaGetSymbolAddress((void**)&xnh,  g_xn_hi);
    cudaGetSymbolAddress((void**)&xnl,  g_xn_lo);
    cudaGetSymbolAddress((void**)&atth, g_att_hi);
    cudaGetSymbolAddress((void**)&attl, g_att_lo);
    cudaGetSymbolAddress((void**)&h1h,  g_h1_hi);
    cudaGetSymbolAddress((void**)&h1l,  g_h1_lo);
    cudaGetSymbolAddress((void**)&wh,   g_w_hi);
    cudaGetSymbolAddress((void**)&wl,   g_w_lo);

    dim3 tb(32, 8);

    wsplit_k<<<(768 * 256 + 255) / 256, 256>>>(w_qkv,  wh + WOFF_QKV,  wl + WOFF_QKV,  768 * 256);
    wsplit_k<<<(256 * 256 + 255) / 256, 256>>>(w_proj, wh + WOFF_PROJ, wl + WOFF_PROJ, 256 * 256);
    wsplit_k<<<(1024 * 256 + 255) / 256, 256>>>(w_mlp1, wh + WOFF_MLP1, wl + WOFF_MLP1, 1024 * 256);
    wsplit_k<<<(256 * 1024 + 255) / 256, 256>>>(w_mlp2, wh + WOFF_MLP2, wl + WOFF_MLP2, 256 * 1024);

    transpose_k<<<dim3(NTOK / 32, CDIM / 32), tb>>>(x, xl, CDIM, NTOK);
    ln_kernel<<<NTOK, CDIM>>>(xl, ln1_g, ln1_b, xnh, xnl);

    // QKV GEMM -> fp32 [4096][768]
    hgemm_tn<0><<<dim3(768 / 64, NTOK / 128), 128>>>(
        xnh, xnl, wh + WOFF_QKV, wl + WOFF_QKV, b_qkv, nullptr,
        qkv, nullptr, nullptr, NTOK, 768, CDIM);

    // K/V split + transpose (coalesced)
    kvsplit_k<<<dim3(NTOK / 64, HEADS), 256>>>(qkv, kh, kl, vh2, vl2);

    attn_mma<<<dim3(NTOK / 128, HEADS), 128>>>(qkv, kh, kl, vh2, vl2, atth, attl);

    hgemm_tn<2><<<dim3(CDIM / 64, NTOK / 128), 128>>>(
        atth, attl, wh + WOFF_PROJ, wl + WOFF_PROJ, b_proj, xl,
        xl, nullptr, nullptr, NTOK, CDIM, CDIM);

    ln_kernel<<<NTOK, CDIM>>>(xl, ln2_g, ln2_b, xnh, xnl);

    hgemm_tn<1><<<dim3(1024 / 64, NTOK / 128), 128>>>(
        xnh, xnl, wh + WOFF_MLP1, wl + WOFF_MLP1, b_mlp1, nullptr,
        nullptr, h1h, h1l, NTOK, 1024, CDIM);

    hgemm_tn<2><<<dim3(CDIM / 64, NTOK / 128), 128>>>(
        h1h, h1l, wh + WOFF_MLP2, wl + WOFF_MLP2, b_mlp2, xl,
        xl, nullptr, nullptr, NTOK, CDIM, 4 * CDIM);

    transpose_k<<<dim3(CDIM / 32, NTOK / 32), tb>>>(xl, out, NTOK, CDIM);
}